// round 5
// baseline (speedup 1.0000x reference)
#include <cuda_runtime.h>
#include <cstdint>

#define N_SAMPLES   8192
#define CODE_LEN    128
#define NUM_CLASSES 1000

// ---- device scratch (no allocations allowed) ----
__device__ unsigned d_used[NUM_CLASSES];
__device__ uint4    d_cwbits[NUM_CLASSES];
__device__ uint4    d_compact[NUM_CLASSES];
__device__ int      d_ucount;
__device__ float    d_bce;
__device__ unsigned d_sig;
__device__ uint4    d_predbits[N_SAMPLES];

// ---------------------------------------------------------------------------
__global__ void k_zero() {
    int t = threadIdx.x;
    if (t < NUM_CLASSES) d_used[t] = 0u;
    if (t == 0) { d_ucount = 0; d_bce = 0.0f; d_sig = 0u; }
}

// Pack one codeword (128 floats in {0,1}) into 128 bits. One warp per codeword.
__global__ void k_pack_cw(const float* __restrict__ cw) {
    int w    = (blockIdx.x * blockDim.x + threadIdx.x) >> 5;
    int lane = threadIdx.x & 31;
    if (w >= NUM_CLASSES) return;
    float4 v = reinterpret_cast<const float4*>(cw + (size_t)w * CODE_LEN)[lane];
    unsigned nib = (unsigned)(v.x > 0.5f)
                 | ((unsigned)(v.y > 0.5f) << 1)
                 | ((unsigned)(v.z > 0.5f) << 2)
                 | ((unsigned)(v.w > 0.5f) << 3);
    unsigned wi = lane >> 3, sh = (lane & 7) * 4;
    unsigned w0 = __reduce_or_sync(0xffffffffu, wi == 0 ? (nib << sh) : 0u);
    unsigned w1 = __reduce_or_sync(0xffffffffu, wi == 1 ? (nib << sh) : 0u);
    unsigned w2 = __reduce_or_sync(0xffffffffu, wi == 2 ? (nib << sh) : 0u);
    unsigned w3 = __reduce_or_sync(0xffffffffu, wi == 3 ? (nib << sh) : 0u);
    if (lane == 0) d_cwbits[w] = make_uint4(w0, w1, w2, w3);
}

// One warp per sample: pred bit-pack, mark used class, BCE row sum.
// NOTE: target is int32 — JAX with x64 disabled downcasts jnp.int64 to int32.
__global__ void k_main(const float* __restrict__ out_p,
                       const int* __restrict__ tgt) {
    __shared__ float wsum[8];
    int gw   = (blockIdx.x * blockDim.x + threadIdx.x) >> 5;
    int lane = threadIdx.x & 31;
    int wid  = threadIdx.x >> 5;

    float bce = 0.0f;
    if (gw < N_SAMPLES) {
        int t = tgt[gw];
        // defensive clamp: an out-of-range t must not fault (gives clean
        // rel_err diagnostic instead if the dtype assumption is ever wrong)
        int tc = (t < 0) ? 0 : ((t >= NUM_CLASSES) ? NUM_CLASSES - 1 : t);

        float4 v = reinterpret_cast<const float4*>(out_p + (size_t)gw * CODE_LEN)[lane];
        unsigned nib = (unsigned)(v.x > 0.5f)
                     | ((unsigned)(v.y > 0.5f) << 1)
                     | ((unsigned)(v.z > 0.5f) << 2)
                     | ((unsigned)(v.w > 0.5f) << 3);
        unsigned wi = lane >> 3, sh = (lane & 7) * 4;
        unsigned w0 = __reduce_or_sync(0xffffffffu, wi == 0 ? (nib << sh) : 0u);
        unsigned w1 = __reduce_or_sync(0xffffffffu, wi == 1 ? (nib << sh) : 0u);
        unsigned w2 = __reduce_or_sync(0xffffffffu, wi == 2 ? (nib << sh) : 0u);
        unsigned w3 = __reduce_or_sync(0xffffffffu, wi == 3 ? (nib << sh) : 0u);
        if (lane == 0) {
            d_predbits[gw] = make_uint4(w0, w1, w2, w3);
            d_used[tc] = 1u;
        }
        // BCE terms for this lane's 4 positions, selected by the target codeword bit.
        uint4 cwb = d_cwbits[tc];
        unsigned word = (&cwb.x)[lane >> 3];
        unsigned base = (lane & 7) * 4;
        float o[4] = { v.x, v.y, v.z, v.w };
        #pragma unroll
        for (int q = 0; q < 4; q++) {
            bool b = (word >> (base + q)) & 1u;
            float oo = o[q];
            bce += b ? -logf(oo) : -log1pf(-oo);
        }
    }
    #pragma unroll
    for (int off = 16; off > 0; off >>= 1)
        bce += __shfl_down_sync(0xffffffffu, bce, off);
    if (lane == 0) wsum[wid] = bce;
    __syncthreads();
    if (wid == 0) {
        float s = (lane < (int)(blockDim.x >> 5)) ? wsum[lane] : 0.0f;
        #pragma unroll
        for (int off = 4; off > 0; off >>= 1)
            s += __shfl_down_sync(0xffffffffu, s, off);
        if (lane == 0) atomicAdd(&d_bce, s);
    }
}

// Compact the used codeword bit-patterns.
__global__ void k_compact() {
    int c = threadIdx.x;
    if (c < NUM_CLASSES && d_used[c]) {
        int p = atomicAdd(&d_ucount, 1);
        if (p < NUM_CLASSES) d_compact[p] = d_cwbits[c];
    }
}

__device__ __forceinline__ unsigned ham4(uint4 a, uint4 b) {
    return __popc(a.x ^ b.x) + __popc(a.y ^ b.y)
         + __popc(a.z ^ b.z) + __popc(a.w ^ b.w);
}

// Thread per sample: min Hamming distance over the used codeword set.
__global__ void k_min() {
    __shared__ uint4 sh[NUM_CLASSES];
    __shared__ unsigned wsum[8];
    int U = d_ucount;
    if (U > NUM_CLASSES) U = NUM_CLASSES;
    for (int k = threadIdx.x; k < U; k += blockDim.x) sh[k] = d_compact[k];
    __syncthreads();

    int i = blockIdx.x * blockDim.x + threadIdx.x;   // < 8192 by construction
    uint4 x = d_predbits[i];
    unsigned mn = 0xffffffffu;
    int k = 0;
    for (; k + 4 <= U; k += 4) {
        unsigned d0 = ham4(x, sh[k]);
        unsigned d1 = ham4(x, sh[k + 1]);
        unsigned d2 = ham4(x, sh[k + 2]);
        unsigned d3 = ham4(x, sh[k + 3]);
        mn = min(mn, min(min(d0, d1), min(d2, d3)));
    }
    for (; k < U; k++) mn = min(mn, ham4(x, sh[k]));

    // sum sigma (exact integer)
    unsigned s = mn;
    #pragma unroll
    for (int off = 16; off > 0; off >>= 1)
        s += __shfl_down_sync(0xffffffffu, s, off);
    int lane = threadIdx.x & 31, wid = threadIdx.x >> 5;
    if (lane == 0) wsum[wid] = s;
    __syncthreads();
    if (wid == 0) {
        unsigned nw = blockDim.x >> 5;
        unsigned t = (lane < (int)nw) ? wsum[lane] : 0u;
        #pragma unroll
        for (int off = 4; off > 0; off >>= 1)
            t += __shfl_down_sync(0xffffffffu, t, off);
        if (lane == 0) atomicAdd(&d_sig, t);
    }
}

__global__ void k_final(float* __restrict__ out) {
    out[0] = (d_bce + (float)CODE_LEN * (float)d_sig)
           / (float)(N_SAMPLES * CODE_LEN);
}

// ---------------------------------------------------------------------------
extern "C" void kernel_launch(void* const* d_in, const int* in_sizes, int n_in,
                              void* d_out, int out_size) {
    const float* out_p = (const float*)d_in[0];   // [8192,128] float32
    const float* cw_p  = (const float*)d_in[1];   // [1000,128] float32
    const int*   tgt_p = (const int*)d_in[2];     // [8192] int32 (JAX x64 off)
    float* res = (float*)d_out;

    k_zero<<<1, 1024>>>();
    k_pack_cw<<<(NUM_CLASSES * 32 + 255) / 256, 256>>>(cw_p);
    k_main<<<(N_SAMPLES * 32) / 256, 256>>>(out_p, tgt_p);
    k_compact<<<1, 1024>>>();
    k_min<<<N_SAMPLES / 256, 256>>>();
    k_final<<<1, 1>>>(res);
}

// round 6
// speedup vs baseline: 2.3148x; 2.3148x over previous
#include <cuda_runtime.h>
#include <cstdint>

#define N_SAMPLES   8192
#define CODE_LEN    128
#define NUM_CLASSES 1000
#define NB_MAIN     1024   // k_main: 1024 blocks x 256 thr = 8192 warps (1/sample)
#define NB_MIN      128    // k_min : 128 blocks x 256 thr, 64 samples/block

// ---- device scratch (zero-initialized at load; self-cleaning each run) ----
__device__ unsigned d_used[NUM_CLASSES];        // set by k_main, zeroed by k_min last block
__device__ uint4    d_cwbits[NUM_CLASSES];
__device__ uint4    d_predbits[N_SAMPLES];
__device__ float    d_bce_part[NB_MAIN];
__device__ unsigned d_sig_part[NB_MIN];
__device__ int      d_done;                     // zeroed by k_min last block

__device__ __forceinline__ unsigned pack_nib(float4 v) {
    return (unsigned)(v.x > 0.5f)
         | ((unsigned)(v.y > 0.5f) << 1)
         | ((unsigned)(v.z > 0.5f) << 2)
         | ((unsigned)(v.w > 0.5f) << 3);
}

// ---------------------------------------------------------------------------
// K1: codeword bit-pack (warps 0..999) + per-sample pred pack, used-mark,
//     BCE row sum (all 8192 warps). BCE reads codeword floats directly so it
//     has no dependency on the packed bits.
__global__ void k_main(const float* __restrict__ out_p,
                       const float* __restrict__ cw,
                       const int*   __restrict__ tgt) {
    __shared__ float wsum[8];
    int gw   = (blockIdx.x * blockDim.x + threadIdx.x) >> 5;  // 0..8191
    int lane = threadIdx.x & 31;
    int wid  = threadIdx.x >> 5;

    // --- pack one codeword (warp-uniform branch) ---
    if (gw < NUM_CLASSES) {
        float4 v = reinterpret_cast<const float4*>(cw + (size_t)gw * CODE_LEN)[lane];
        unsigned nib = pack_nib(v);
        unsigned wi = lane >> 3, sh = (lane & 7) * 4;
        unsigned w0 = __reduce_or_sync(0xffffffffu, wi == 0 ? (nib << sh) : 0u);
        unsigned w1 = __reduce_or_sync(0xffffffffu, wi == 1 ? (nib << sh) : 0u);
        unsigned w2 = __reduce_or_sync(0xffffffffu, wi == 2 ? (nib << sh) : 0u);
        unsigned w3 = __reduce_or_sync(0xffffffffu, wi == 3 ? (nib << sh) : 0u);
        if (lane == 0) d_cwbits[gw] = make_uint4(w0, w1, w2, w3);
    }

    // --- per-sample work (gw always < 8192 by grid construction) ---
    int t  = tgt[gw];
    int tc = (t < 0) ? 0 : ((t >= NUM_CLASSES) ? NUM_CLASSES - 1 : t);

    float4 v = reinterpret_cast<const float4*>(out_p + (size_t)gw * CODE_LEN)[lane];
    unsigned nib = pack_nib(v);
    unsigned wi = lane >> 3, sh = (lane & 7) * 4;
    unsigned w0 = __reduce_or_sync(0xffffffffu, wi == 0 ? (nib << sh) : 0u);
    unsigned w1 = __reduce_or_sync(0xffffffffu, wi == 1 ? (nib << sh) : 0u);
    unsigned w2 = __reduce_or_sync(0xffffffffu, wi == 2 ? (nib << sh) : 0u);
    unsigned w3 = __reduce_or_sync(0xffffffffu, wi == 3 ? (nib << sh) : 0u);
    if (lane == 0) {
        d_predbits[gw] = make_uint4(w0, w1, w2, w3);
        d_used[tc] = 1u;
    }

    // BCE from codeword floats (coalesced 512B row, L2-resident table)
    float4 c4 = reinterpret_cast<const float4*>(cw + (size_t)tc * CODE_LEN)[lane];
    float bce = 0.0f;
    bce += (c4.x > 0.5f) ? -logf(v.x) : -log1pf(-v.x);
    bce += (c4.y > 0.5f) ? -logf(v.y) : -log1pf(-v.y);
    bce += (c4.z > 0.5f) ? -logf(v.z) : -log1pf(-v.z);
    bce += (c4.w > 0.5f) ? -logf(v.w) : -log1pf(-v.w);

    #pragma unroll
    for (int off = 16; off > 0; off >>= 1)
        bce += __shfl_down_sync(0xffffffffu, bce, off);
    if (lane == 0) wsum[wid] = bce;
    __syncthreads();
    if (wid == 0) {
        float s = (lane < 8) ? wsum[lane] : 0.0f;
        #pragma unroll
        for (int off = 4; off > 0; off >>= 1)
            s += __shfl_down_sync(0xffffffffu, s, off);
        if (lane == 0) d_bce_part[blockIdx.x] = s;
    }
}

__device__ __forceinline__ unsigned ham4(uint4 a, uint4 b) {
    return __popc(a.x ^ b.x) + __popc(a.y ^ b.y)
         + __popc(a.z ^ b.z) + __popc(a.w ^ b.w);
}

// ---------------------------------------------------------------------------
// K2: per-block ballot-compaction of used codewords into smem, 4-threads-per-
//     sample min Hamming scan, per-block sigma partial, last-block final
//     reduction + state reset (threadfence-reduction pattern).
__global__ void __launch_bounds__(256) k_min(float* __restrict__ out) {
    __shared__ uint4    cwl[NUM_CLASSES];
    __shared__ int      cnt;
    __shared__ unsigned ured[8];
    __shared__ float    fred[8];
    __shared__ int      last_flag;

    int tid  = threadIdx.x;
    int lane = tid & 31, wid = tid >> 5;
    if (tid == 0) cnt = 0;
    __syncthreads();

    // --- local compaction of used codeword bit-patterns ---
    #pragma unroll
    for (int c = tid; c < 1024; c += 256) {
        bool p = (c < NUM_CLASSES) && (d_used[c] != 0u);
        unsigned bal = __ballot_sync(0xffffffffu, p);
        int base;
        if (lane == 0) base = atomicAdd(&cnt, __popc(bal));
        base = __shfl_sync(0xffffffffu, base, 0);
        if (p) {
            int pos = base + __popc(bal & ((1u << lane) - 1u));
            cwl[pos] = d_cwbits[c];
        }
    }
    __syncthreads();
    int U = cnt;

    // --- min over used set: 4 threads per sample ---
    int s   = blockIdx.x * 64 + (tid >> 2);
    int sub = tid & 3;
    uint4 x = d_predbits[s];
    unsigned mn = 0xffffffffu;
    for (int k = sub; k < U; k += 4)
        mn = min(mn, ham4(x, cwl[k]));
    mn = min(mn, __shfl_xor_sync(0xffffffffu, mn, 1));
    mn = min(mn, __shfl_xor_sync(0xffffffffu, mn, 2));

    // --- block sigma sum (count each sample once) ---
    unsigned v = (sub == 0) ? mn : 0u;
    #pragma unroll
    for (int off = 16; off > 0; off >>= 1)
        v += __shfl_down_sync(0xffffffffu, v, off);
    if (lane == 0) ured[wid] = v;
    __syncthreads();
    if (tid == 0) {
        unsigned tot = 0;
        #pragma unroll
        for (int w = 0; w < 8; w++) tot += ured[w];
        d_sig_part[blockIdx.x] = tot;
        __threadfence();
        int old = atomicAdd(&d_done, 1);
        last_flag = (old == NB_MIN - 1);
    }
    __syncthreads();

    // --- last block: final reduction, output, state reset ---
    if (last_flag) {
        float fb = 0.0f;
        for (int i = tid; i < NB_MAIN; i += 256) fb += d_bce_part[i];
        unsigned sg = (tid < NB_MIN) ? d_sig_part[tid] : 0u;

        #pragma unroll
        for (int off = 16; off > 0; off >>= 1) {
            fb += __shfl_down_sync(0xffffffffu, fb, off);
            sg += __shfl_down_sync(0xffffffffu, sg, off);
        }
        if (lane == 0) { fred[wid] = fb; ured[wid] = sg; }
        __syncthreads();
        if (tid == 0) {
            float ftot = 0.0f; unsigned stot = 0;
            #pragma unroll
            for (int w = 0; w < 8; w++) { ftot += fred[w]; stot += ured[w]; }
            out[0] = (ftot + (float)CODE_LEN * (float)stot)
                   / (float)(N_SAMPLES * CODE_LEN);
            d_done = 0;                      // reset for next replay
        }
        for (int c = tid; c < NUM_CLASSES; c += 256)
            d_used[c] = 0u;                  // reset for next replay
    }
}

// ---------------------------------------------------------------------------
extern "C" void kernel_launch(void* const* d_in, const int* in_sizes, int n_in,
                              void* d_out, int out_size) {
    const float* out_p = (const float*)d_in[0];   // [8192,128] float32
    const float* cw_p  = (const float*)d_in[1];   // [1000,128] float32
    const int*   tgt_p = (const int*)d_in[2];     // [8192] int32

    k_main<<<NB_MAIN, 256>>>(out_p, cw_p, tgt_p);
    k_min<<<NB_MIN, 256>>>((float*)d_out);
}